// round 14
// baseline (speedup 1.0000x reference)
#include <cuda_runtime.h>
#include <cuda_fp16.h>

#define NN    100000
#define EEMAX 3200000
#define F1    16
#define F2    40
#define DIN   512
#define CAP   128               // bucket capacity; deg ~ Poisson(32), P(>128) ~ 0

// Scratch (static device globals — no allocation allowed)
__device__ int    g_cnt [NN];          // edge in-degree (without self-loop)
__device__ int    g_adj [NN * CAP];    // bucketed adjacency: sources per target
__device__ float  g_dinv[NN];
__device__ float  g_xw  [NN * F1];     // x @ W1 (fp32, unscaled)
__device__ __half g_src [NN * F1];     // fp16: dinv * xw
__device__ __half g_hds [NN * F1];     // fp16: dinv * dropout(h + b1)

// ---------------------------------------------------------------------------
// Single-pass adjacency build: count + bucket-append (no scan, no second pass)
__global__ void k_fill(const int* __restrict__ row, const int* __restrict__ col,
                       int E4, int E) {
    int i = blockIdx.x * blockDim.x + threadIdx.x;
    if (i < E4) {
        int4 r = ((const int4*)row)[i];
        int4 c = ((const int4*)col)[i];
        int p;
        p = atomicAdd(&g_cnt[c.x], 1); if (p < CAP) g_adj[c.x * CAP + p] = r.x;
        p = atomicAdd(&g_cnt[c.y], 1); if (p < CAP) g_adj[c.y * CAP + p] = r.y;
        p = atomicAdd(&g_cnt[c.z], 1); if (p < CAP) g_adj[c.z * CAP + p] = r.z;
        p = atomicAdd(&g_cnt[c.w], 1); if (p < CAP) g_adj[c.w * CAP + p] = r.w;
    } else {
        int e = E4 * 4 + (i - E4);               // tail (E%4 != 0 only)
        if (e < E) {
            int c = col[e], p = atomicAdd(&g_cnt[c], 1);
            if (p < CAP) g_adj[c * CAP + p] = row[e];
        }
    }
}

// ---------------------------------------------------------------------------
__device__ __forceinline__ unsigned cvt2(float lo, float hi) {
    __half2 h = __floats2half2_rn(lo, hi);
    return *(unsigned*)&h;
}

// gemm1 v7 (TENSOR CORE, k-permuted float4 A-loads, deep unroll):
// lane l's fragment slots map to PHYSICAL k = 4*(l%4)+{0..3}; same permutation
// applied to the B smem table -> one contiguous float4 per row per k-step.
__global__ __launch_bounds__(256) void k_gemm1(const float* __restrict__ x,
                                               const float* __restrict__ W1) {
    __shared__ unsigned sB[32][2][2][32];        // [kstep][nhalf][breg][lane] 16KB

    int t = threadIdx.x;
    // pack B fragments with permuted k: slot (r,b) of lane l -> phys k = 4*(l&3)+2r+b
    for (int i = t; i < 32 * 2 * 2 * 32; i += 256) {
        int l = i & 31;
        int r = (i >> 5) & 1;
        int h = (i >> 6) & 1;
        int j = i >> 7;
        int kp = j * 16 + 4 * (l & 3) + 2 * r;   // physical k (permuted)
        int n  = h * 8 + (l >> 2);
        ((unsigned*)sB)[i] = cvt2(W1[kp * 16 + n], W1[(kp + 1) * 16 + n]);
    }
    __syncthreads();

    int w = t >> 5, l = t & 31;
    int v0 = blockIdx.x * 128 + w * 16;          // this warp's 16 nodes
    int gr = l >> 2;                             // fragment row group 0..7
    int ca = 4 * (l & 3);                        // A-load offset (physical k)
    int co = 2 * (l & 3);                        // output col pair base
    int v_lo = v0 + gr, v_hi = v0 + gr + 8;
    const float* plo = x + (size_t)min(v_lo, NN - 1) * DIN;
    const float* phi = x + (size_t)min(v_hi, NN - 1) * DIN;

    float d0 = 0.f, d1 = 0.f, d2 = 0.f, d3 = 0.f;   // n-half 0 accums
    float e0 = 0.f, e1 = 0.f, e2 = 0.f, e3 = 0.f;   // n-half 1 accums

#pragma unroll 8
    for (int j = 0; j < 32; ++j) {               // k-steps of 16
        int k0 = j * 16;
        float4 flo = *(const float4*)(plo + k0 + ca);
        float4 fhi = *(const float4*)(phi + k0 + ca);
        unsigned a0 = cvt2(flo.x, flo.y);
        unsigned a1 = cvt2(fhi.x, fhi.y);
        unsigned a2 = cvt2(flo.z, flo.w);
        unsigned a3 = cvt2(fhi.z, fhi.w);
        unsigned b00 = sB[j][0][0][l], b01 = sB[j][0][1][l];
        unsigned b10 = sB[j][1][0][l], b11 = sB[j][1][1][l];
        asm volatile(
            "mma.sync.aligned.m16n8k16.row.col.f32.f16.f16.f32 "
            "{%0,%1,%2,%3}, {%4,%5,%6,%7}, {%8,%9}, {%0,%1,%2,%3};"
            : "+f"(d0), "+f"(d1), "+f"(d2), "+f"(d3)
            : "r"(a0), "r"(a1), "r"(a2), "r"(a3), "r"(b00), "r"(b01));
        asm volatile(
            "mma.sync.aligned.m16n8k16.row.col.f32.f16.f16.f32 "
            "{%0,%1,%2,%3}, {%4,%5,%6,%7}, {%8,%9}, {%0,%1,%2,%3};"
            : "+f"(e0), "+f"(e1), "+f"(e2), "+f"(e3)
            : "r"(a0), "r"(a1), "r"(a2), "r"(a3), "r"(b10), "r"(b11));
    }

    if (v_lo < NN) {
        *(float2*)(g_xw + (size_t)v_lo * F1 + co)     = make_float2(d0, d1);
        *(float2*)(g_xw + (size_t)v_lo * F1 + 8 + co) = make_float2(e0, e1);
    }
    if (v_hi < NN) {
        *(float2*)(g_xw + (size_t)v_hi * F1 + co)     = make_float2(d2, d3);
        *(float2*)(g_xw + (size_t)v_hi * F1 + 8 + co) = make_float2(e2, e3);
    }
}

// scale: dinv = rsqrt(cnt+1); g_src = fp16(dinv * g_xw)   (one thread per node)
__global__ void k_scale() {
    int v = blockIdx.x * blockDim.x + threadIdx.x;
    if (v >= NN) return;
    float d = rsqrtf((float)(g_cnt[v] + 1));
    g_dinv[v] = d;
    const float4* xp = (const float4*)(g_xw + (size_t)v * F1);
    uint4 o[2];
    __half2* hp = (__half2*)o;
#pragma unroll
    for (int q = 0; q < 4; ++q) {
        float4 a = xp[q];
        hp[q * 2 + 0] = __floats2half2_rn(d * a.x, d * a.y);
        hp[q * 2 + 1] = __floats2half2_rn(d * a.z, d * a.w);
    }
    ((uint4*)g_src)[v * 2 + 0] = o[0];
    ((uint4*)g_src)[v * 2 + 1] = o[1];
}

// ---------------------------------------------------------------------------
// JAX threefry2x32 (partitionable): key=(0,42), ctr=(0, idx).
// bernoulli(0.5) keep  <=>  MSB(out0 ^ out1) == 0
__device__ __forceinline__ unsigned tf_keep_bits(unsigned idx) {
    const unsigned k0 = 0u, k1 = 42u, k2 = 0u ^ 42u ^ 0x1BD11BDAu;
    unsigned x0 = k0;
    unsigned x1 = idx + k1;
#define TFR(r) { x0 += x1; x1 = (x1 << (r)) | (x1 >> (32 - (r))); x1 ^= x0; }
    TFR(13) TFR(15) TFR(26) TFR(6)   x0 += k1; x1 += k2 + 1u;
    TFR(17) TFR(29) TFR(16) TFR(24)  x0 += k2; x1 += k0 + 2u;
    TFR(13) TFR(15) TFR(26) TFR(6)   x0 += k0; x1 += k1 + 3u;
    TFR(17) TFR(29) TFR(16) TFR(24)  x0 += k1; x1 += k2 + 4u;
    TFR(13) TFR(15) TFR(26) TFR(6)   x0 += k2; x1 += k0 + 5u;
#undef TFR
    return x0 ^ x1;
}

// ---------------------------------------------------------------------------
// fp16 gather: 4 threads/node, q in [0,4) owns 4 halves (8B).
// 16-deep unroll (MLP=16; deg~32 -> 2 main iterations), int4 adjacency loads.
__device__ __forceinline__ void h4acc(uint2 u, float4& acc) {
    float2 f0 = __half22float2(*(__half2*)&u.x);
    float2 f1 = __half22float2(*(__half2*)&u.y);
    acc.x += f0.x; acc.y += f0.y; acc.z += f1.x; acc.w += f1.y;
}

#define AGG_LOOP(SRCP)                                                         \
    float4 acc = make_float4(0.f, 0.f, 0.f, 0.f);                              \
    { uint2 us = SRCP[t * 4 + q]; h4acc(us, acc); }   /* self-loop */          \
    {                                                                          \
        int cnt = g_cnt[t]; if (cnt > CAP) cnt = CAP;                          \
        const int* ap = g_adj + t * CAP;                                       \
        int pos = 0;                                                           \
        for (; pos + 16 <= cnt; pos += 16) {                                   \
            int4 a0 = ((const int4*)(ap + pos))[0];                            \
            int4 a1 = ((const int4*)(ap + pos))[1];                            \
            int4 a2 = ((const int4*)(ap + pos))[2];                            \
            int4 a3 = ((const int4*)(ap + pos))[3];                            \
            uint2 u0 = SRCP[a0.x*4+q], u1 = SRCP[a0.y*4+q];                    \
            uint2 u2 = SRCP[a0.z*4+q], u3 = SRCP[a0.w*4+q];                    \
            uint2 u4 = SRCP[a1.x*4+q], u5 = SRCP[a1.y*4+q];                    \
            uint2 u6 = SRCP[a1.z*4+q], u7 = SRCP[a1.w*4+q];                    \
            uint2 u8 = SRCP[a2.x*4+q], u9 = SRCP[a2.y*4+q];                    \
            uint2 uA = SRCP[a2.z*4+q], uB = SRCP[a2.w*4+q];                    \
            uint2 uC = SRCP[a3.x*4+q], uD = SRCP[a3.y*4+q];                    \
            uint2 uE = SRCP[a3.z*4+q], uF = SRCP[a3.w*4+q];                    \
            h4acc(u0, acc); h4acc(u1, acc); h4acc(u2, acc); h4acc(u3, acc);    \
            h4acc(u4, acc); h4acc(u5, acc); h4acc(u6, acc); h4acc(u7, acc);    \
            h4acc(u8, acc); h4acc(u9, acc); h4acc(uA, acc); h4acc(uB, acc);    \
            h4acc(uC, acc); h4acc(uD, acc); h4acc(uE, acc); h4acc(uF, acc);    \
        }                                                                      \
        for (; pos + 8 <= cnt; pos += 8) {                                     \
            int4 a0 = ((const int4*)(ap + pos))[0];                            \
            int4 a1 = ((const int4*)(ap + pos))[1];                            \
            uint2 u0 = SRCP[a0.x*4+q], u1 = SRCP[a0.y*4+q];                    \
            uint2 u2 = SRCP[a0.z*4+q], u3 = SRCP[a0.w*4+q];                    \
            uint2 u4 = SRCP[a1.x*4+q], u5 = SRCP[a1.y*4+q];                    \
            uint2 u6 = SRCP[a1.z*4+q], u7 = SRCP[a1.w*4+q];                    \
            h4acc(u0, acc); h4acc(u1, acc); h4acc(u2, acc); h4acc(u3, acc);    \
            h4acc(u4, acc); h4acc(u5, acc); h4acc(u6, acc); h4acc(u7, acc);    \
        }                                                                      \
        for (; pos < cnt; ++pos) { uint2 u = SRCP[ap[pos]*4+q]; h4acc(u, acc);}\
    }

// Layer-1 aggregation (4 threads per node) + dropout fused; fp16 out.
__global__ __launch_bounds__(256) void k_agg1(const float* __restrict__ b1) {
    int t = blockIdx.x * 64 + (threadIdx.x >> 2);
    int q = threadIdx.x & 3;
    if (t >= NN) return;

    const uint2* src = (const uint2*)g_src;
    AGG_LOOP(src)

    float d = g_dinv[t];
    float4 bb = ((const float4*)b1)[q];
    unsigned idx = (unsigned)(t * 16 + q * 4);
    float h0 = d * acc.x + bb.x, h1 = d * acc.y + bb.y;
    float h2 = d * acc.z + bb.z, h3 = d * acc.w + bb.w;
    float o0 = (tf_keep_bits(idx + 0) & 0x80000000u) ? 0.0f : 2.0f * d * h0;
    float o1 = (tf_keep_bits(idx + 1) & 0x80000000u) ? 0.0f : 2.0f * d * h1;
    float o2 = (tf_keep_bits(idx + 2) & 0x80000000u) ? 0.0f : 2.0f * d * h2;
    float o3 = (tf_keep_bits(idx + 3) & 0x80000000u) ? 0.0f : 2.0f * d * h3;
    uint2 o;
    ((__half2*)&o.x)[0] = __floats2half2_rn(o0, o1);
    ((__half2*)&o.y)[0] = __floats2half2_rn(o2, o3);
    ((uint2*)g_hds)[t * 4 + q] = o;
}

// Layer-2 aggregation + fused (16x40 GEMM + b2); fp32 out written directly.
__global__ __launch_bounds__(256) void k_agg2(const float* __restrict__ W2,
                                              const float* __restrict__ b2,
                                              float* __restrict__ out) {
    __shared__ float sW[F1 * F2];
    __shared__ float sb[F2];
    for (int i = threadIdx.x; i < F1 * F2; i += 256) sW[i] = W2[i];
    if (threadIdx.x < F2) sb[threadIdx.x] = b2[threadIdx.x];
    __syncthreads();

    int tid = blockIdx.x * 64 + (threadIdx.x >> 2);
    int q   = threadIdx.x & 3;
    bool valid = tid < NN;
    int t = valid ? tid : NN - 1;

    const uint2* src = (const uint2*)g_hds;
    AGG_LOOP(src)

    float d = g_dinv[t];
    acc.x *= d; acc.y *= d; acc.z *= d; acc.w *= d;

    // assemble all 16 features into each lane via width-4 shuffles
    float gg[16];
#pragma unroll
    for (int s = 0; s < 4; ++s) {
        gg[s*4+0] = __shfl_sync(0xffffffffu, acc.x, s, 4);
        gg[s*4+1] = __shfl_sync(0xffffffffu, acc.y, s, 4);
        gg[s*4+2] = __shfl_sync(0xffffffffu, acc.z, s, 4);
        gg[s*4+3] = __shfl_sync(0xffffffffu, acc.w, s, 4);
    }

    // each lane computes 10 of the 40 outputs
    float o[10];
#pragma unroll
    for (int j = 0; j < 10; ++j) o[j] = sb[q * 10 + j];
#pragma unroll
    for (int k = 0; k < 16; ++k) {
        float gv = gg[k];
        const float* wr = sW + k * F2 + q * 10;
#pragma unroll
        for (int j = 0; j < 10; ++j) o[j] += gv * wr[j];
    }

    if (valid) {
        float* op = out + (size_t)t * F2 + q * 10;
#pragma unroll
        for (int j = 0; j < 10; ++j) op[j] = o[j];
    }
}

// ---------------------------------------------------------------------------
extern "C" void kernel_launch(void* const* d_in, const int* in_sizes, int n_in,
                              void* d_out, int out_size) {
    const float* x  = (const float*)d_in[0];
    const int*   ei = (const int*)  d_in[1];
    const float* W1 = (const float*)d_in[2];
    const float* b1 = (const float*)d_in[3];
    const float* W2 = (const float*)d_in[4];
    const float* b2 = (const float*)d_in[5];
    float* out = (float*)d_out;

    int E = in_sizes[1] / 2;                  // 3,200,000
    if (E > EEMAX) E = EEMAX;
    const int* row = ei;
    const int* col = ei + E;
    int E4 = E / 4;

    const int TB = 256;
    int nb_g  = (NN + 127) / 128;             // gemm1 blocks (128 nodes each)
    int nb_n  = (NN + TB - 1) / TB;
    int nb_e4 = (E4 + (E - E4 * 4) + TB - 1) / TB;
    int nb_a  = (NN + 63) / 64;               // agg blocks (4 thr/node)

    // one-time host-side resources (created on first call, reused by capture)
    static cudaStream_t sB = nullptr;
    static cudaEvent_t evStart = nullptr, evGemm = nullptr;
    static void* cntPtr = nullptr;
    if (!sB) {
        cudaStreamCreateWithFlags(&sB, cudaStreamNonBlocking);
        cudaEventCreateWithFlags(&evStart, cudaEventDisableTiming);
        cudaEventCreateWithFlags(&evGemm,  cudaEventDisableTiming);
        cudaGetSymbolAddress(&cntPtr, g_cnt);
    }

    cudaEventRecord(evStart, 0);              // fork point (t = 0)
    cudaStreamWaitEvent(sB, evStart, 0);

    // main stream: one-pass bucketed adjacency build (launches 1-2)
    cudaMemsetAsync(cntPtr, 0, NN * sizeof(int), 0);
    k_fill  <<<nb_e4, TB>>>(row, col, E4, E);

    // side stream (launch 3): tensor-core gemm1, starts at t=0
    k_gemm1 <<<nb_g, TB, 0, sB>>>(x, W1);     // g_xw = x @ W1 (HMMA)
    cudaEventRecord(evGemm, sB);

    cudaStreamWaitEvent(0, evGemm, 0);        // join gemm1
    k_scale <<<nb_n, TB>>>();                 // (launch 4) dinv + fp16 src
    k_agg1  <<<nb_a, TB>>>(b1);               // (launch 5 = ncu slot) agg1
    k_agg2  <<<nb_a, TB>>>(W2, b2, out);      // out (GEMM fused)
}

// round 15
// speedup vs baseline: 1.0113x; 1.0113x over previous
#include <cuda_runtime.h>
#include <cuda_fp16.h>

#define NN    100000
#define EEMAX 3200000
#define F1    16
#define F2    40
#define DIN   512
#define CAP   128               // bucket capacity; deg ~ Poisson(32), P(>128) ~ 0

// Scratch (static device globals — no allocation allowed)
__device__ int    g_cnt [NN];          // edge in-degree (without self-loop)
__device__ int    g_adj [NN * CAP];    // bucketed adjacency: sources per target
__device__ float  g_dinv[NN];
__device__ float  g_xw  [NN * F1];     // x @ W1 (fp32, unscaled)
__device__ __half g_src [NN * F1];     // fp16: dinv * xw
__device__ __half g_hds [NN * F1];     // fp16: dinv * dropout(h + b1)

// ---------------------------------------------------------------------------
// Single-pass adjacency build: count + bucket-append (no scan, no second pass)
__global__ void k_fill(const int* __restrict__ row, const int* __restrict__ col,
                       int E4, int E) {
    int i = blockIdx.x * blockDim.x + threadIdx.x;
    if (i < E4) {
        int4 r = ((const int4*)row)[i];
        int4 c = ((const int4*)col)[i];
        int p;
        p = atomicAdd(&g_cnt[c.x], 1); if (p < CAP) g_adj[c.x * CAP + p] = r.x;
        p = atomicAdd(&g_cnt[c.y], 1); if (p < CAP) g_adj[c.y * CAP + p] = r.y;
        p = atomicAdd(&g_cnt[c.z], 1); if (p < CAP) g_adj[c.z * CAP + p] = r.z;
        p = atomicAdd(&g_cnt[c.w], 1); if (p < CAP) g_adj[c.w * CAP + p] = r.w;
    } else {
        int e = E4 * 4 + (i - E4);               // tail (E%4 != 0 only)
        if (e < E) {
            int c = col[e], p = atomicAdd(&g_cnt[c], 1);
            if (p < CAP) g_adj[c * CAP + p] = row[e];
        }
    }
}

// ---------------------------------------------------------------------------
__device__ __forceinline__ unsigned cvt2(float lo, float hi) {
    __half2 h = __floats2half2_rn(lo, hi);
    return *(unsigned*)&h;
}

// gemm1 (TENSOR CORE, k-permuted float4 A-loads) — R13-validated config.
// lane l's fragment slots map to PHYSICAL k = 4*(l%4)+{0..3}; same permutation
// applied to the B smem table -> one contiguous float4 per row per k-step.
__global__ __launch_bounds__(256) void k_gemm1(const float* __restrict__ x,
                                               const float* __restrict__ W1) {
    __shared__ unsigned sB[32][2][2][32];        // [kstep][nhalf][breg][lane] 16KB

    int t = threadIdx.x;
    // pack B fragments with permuted k: slot (r,b) of lane l -> phys k = 4*(l&3)+2r+b
    for (int i = t; i < 32 * 2 * 2 * 32; i += 256) {
        int l = i & 31;
        int r = (i >> 5) & 1;
        int h = (i >> 6) & 1;
        int j = i >> 7;
        int kp = j * 16 + 4 * (l & 3) + 2 * r;   // physical k (permuted)
        int n  = h * 8 + (l >> 2);
        ((unsigned*)sB)[i] = cvt2(W1[kp * 16 + n], W1[(kp + 1) * 16 + n]);
    }
    __syncthreads();

    int w = t >> 5, l = t & 31;
    int v0 = blockIdx.x * 128 + w * 16;          // this warp's 16 nodes
    int gr = l >> 2;                             // fragment row group 0..7
    int ca = 4 * (l & 3);                        // A-load offset (physical k)
    int co = 2 * (l & 3);                        // output col pair base
    int v_lo = v0 + gr, v_hi = v0 + gr + 8;
    const float* plo = x + (size_t)min(v_lo, NN - 1) * DIN;
    const float* phi = x + (size_t)min(v_hi, NN - 1) * DIN;

    float d0 = 0.f, d1 = 0.f, d2 = 0.f, d3 = 0.f;   // n-half 0 accums
    float e0 = 0.f, e1 = 0.f, e2 = 0.f, e3 = 0.f;   // n-half 1 accums

#pragma unroll 4
    for (int j = 0; j < 32; ++j) {               // k-steps of 16
        int k0 = j * 16;
        float4 flo = *(const float4*)(plo + k0 + ca);
        float4 fhi = *(const float4*)(phi + k0 + ca);
        unsigned a0 = cvt2(flo.x, flo.y);
        unsigned a1 = cvt2(fhi.x, fhi.y);
        unsigned a2 = cvt2(flo.z, flo.w);
        unsigned a3 = cvt2(fhi.z, fhi.w);
        unsigned b00 = sB[j][0][0][l], b01 = sB[j][0][1][l];
        unsigned b10 = sB[j][1][0][l], b11 = sB[j][1][1][l];
        asm volatile(
            "mma.sync.aligned.m16n8k16.row.col.f32.f16.f16.f32 "
            "{%0,%1,%2,%3}, {%4,%5,%6,%7}, {%8,%9}, {%0,%1,%2,%3};"
            : "+f"(d0), "+f"(d1), "+f"(d2), "+f"(d3)
            : "r"(a0), "r"(a1), "r"(a2), "r"(a3), "r"(b00), "r"(b01));
        asm volatile(
            "mma.sync.aligned.m16n8k16.row.col.f32.f16.f16.f32 "
            "{%0,%1,%2,%3}, {%4,%5,%6,%7}, {%8,%9}, {%0,%1,%2,%3};"
            : "+f"(e0), "+f"(e1), "+f"(e2), "+f"(e3)
            : "r"(a0), "r"(a1), "r"(a2), "r"(a3), "r"(b10), "r"(b11));
    }

    if (v_lo < NN) {
        *(float2*)(g_xw + (size_t)v_lo * F1 + co)     = make_float2(d0, d1);
        *(float2*)(g_xw + (size_t)v_lo * F1 + 8 + co) = make_float2(e0, e1);
    }
    if (v_hi < NN) {
        *(float2*)(g_xw + (size_t)v_hi * F1 + co)     = make_float2(d2, d3);
        *(float2*)(g_xw + (size_t)v_hi * F1 + 8 + co) = make_float2(e2, e3);
    }
}

// scale: dinv = rsqrt(cnt+1); g_src = fp16(dinv * g_xw)   (one thread per node)
__global__ void k_scale() {
    int v = blockIdx.x * blockDim.x + threadIdx.x;
    if (v >= NN) return;
    float d = rsqrtf((float)(g_cnt[v] + 1));
    g_dinv[v] = d;
    const float4* xp = (const float4*)(g_xw + (size_t)v * F1);
    uint4 o[2];
    __half2* hp = (__half2*)o;
#pragma unroll
    for (int q = 0; q < 4; ++q) {
        float4 a = xp[q];
        hp[q * 2 + 0] = __floats2half2_rn(d * a.x, d * a.y);
        hp[q * 2 + 1] = __floats2half2_rn(d * a.z, d * a.w);
    }
    ((uint4*)g_src)[v * 2 + 0] = o[0];
    ((uint4*)g_src)[v * 2 + 1] = o[1];
}

// ---------------------------------------------------------------------------
// JAX threefry2x32 (partitionable): key=(0,42), ctr=(0, idx).
// bernoulli(0.5) keep  <=>  MSB(out0 ^ out1) == 0
__device__ __forceinline__ unsigned tf_keep_bits(unsigned idx) {
    const unsigned k0 = 0u, k1 = 42u, k2 = 0u ^ 42u ^ 0x1BD11BDAu;
    unsigned x0 = k0;
    unsigned x1 = idx + k1;
#define TFR(r) { x0 += x1; x1 = (x1 << (r)) | (x1 >> (32 - (r))); x1 ^= x0; }
    TFR(13) TFR(15) TFR(26) TFR(6)   x0 += k1; x1 += k2 + 1u;
    TFR(17) TFR(29) TFR(16) TFR(24)  x0 += k2; x1 += k0 + 2u;
    TFR(13) TFR(15) TFR(26) TFR(6)   x0 += k0; x1 += k1 + 3u;
    TFR(17) TFR(29) TFR(16) TFR(24)  x0 += k1; x1 += k2 + 4u;
    TFR(13) TFR(15) TFR(26) TFR(6)   x0 += k2; x1 += k0 + 5u;
#undef TFR
    return x0 ^ x1;
}

// ---------------------------------------------------------------------------
// fp16 gather: 4 threads/node, q in [0,4) owns 4 halves (8B). 8-deep unroll,
// adjacency read as int4 (R13-validated config).
__device__ __forceinline__ void h4acc(uint2 u, float4& acc) {
    float2 f0 = __half22float2(*(__half2*)&u.x);
    float2 f1 = __half22float2(*(__half2*)&u.y);
    acc.x += f0.x; acc.y += f0.y; acc.z += f1.x; acc.w += f1.y;
}

#define AGG_LOOP(SRCP)                                                         \
    float4 acc = make_float4(0.f, 0.f, 0.f, 0.f);                              \
    { uint2 us = SRCP[t * 4 + q]; h4acc(us, acc); }   /* self-loop */          \
    {                                                                          \
        int cnt = g_cnt[t]; if (cnt > CAP) cnt = CAP;                          \
        const int* ap = g_adj + t * CAP;                                       \
        int pos = 0;                                                           \
        for (; pos + 8 <= cnt; pos += 8) {                                     \
            int4 a0 = ((const int4*)(ap + pos))[0];                            \
            int4 a1 = ((const int4*)(ap + pos))[1];                            \
            uint2 u0 = SRCP[a0.x*4+q], u1 = SRCP[a0.y*4+q];                    \
            uint2 u2 = SRCP[a0.z*4+q], u3 = SRCP[a0.w*4+q];                    \
            uint2 u4 = SRCP[a1.x*4+q], u5 = SRCP[a1.y*4+q];                    \
            uint2 u6 = SRCP[a1.z*4+q], u7 = SRCP[a1.w*4+q];                    \
            h4acc(u0, acc); h4acc(u1, acc); h4acc(u2, acc); h4acc(u3, acc);    \
            h4acc(u4, acc); h4acc(u5, acc); h4acc(u6, acc); h4acc(u7, acc);    \
        }                                                                      \
        for (; pos < cnt; ++pos) { uint2 u = SRCP[ap[pos]*4+q]; h4acc(u, acc);}\
    }

// Layer-1 aggregation (4 threads per node) + dropout fused; fp16 out.
__global__ __launch_bounds__(256) void k_agg1(const float* __restrict__ b1) {
    int t = blockIdx.x * 64 + (threadIdx.x >> 2);
    int q = threadIdx.x & 3;
    if (t >= NN) return;

    const uint2* src = (const uint2*)g_src;
    AGG_LOOP(src)

    float d = g_dinv[t];
    float4 bb = ((const float4*)b1)[q];
    unsigned idx = (unsigned)(t * 16 + q * 4);
    float h0 = d * acc.x + bb.x, h1 = d * acc.y + bb.y;
    float h2 = d * acc.z + bb.z, h3 = d * acc.w + bb.w;
    float o0 = (tf_keep_bits(idx + 0) & 0x80000000u) ? 0.0f : 2.0f * d * h0;
    float o1 = (tf_keep_bits(idx + 1) & 0x80000000u) ? 0.0f : 2.0f * d * h1;
    float o2 = (tf_keep_bits(idx + 2) & 0x80000000u) ? 0.0f : 2.0f * d * h2;
    float o3 = (tf_keep_bits(idx + 3) & 0x80000000u) ? 0.0f : 2.0f * d * h3;
    uint2 o;
    ((__half2*)&o.x)[0] = __floats2half2_rn(o0, o1);
    ((__half2*)&o.y)[0] = __floats2half2_rn(o2, o3);
    ((uint2*)g_hds)[t * 4 + q] = o;
}

// Layer-2 aggregation + fused (16x40 GEMM + b2); fp32 out written directly.
__global__ __launch_bounds__(256) void k_agg2(const float* __restrict__ W2,
                                              const float* __restrict__ b2,
                                              float* __restrict__ out) {
    __shared__ float sW[F1 * F2];
    __shared__ float sb[F2];
    for (int i = threadIdx.x; i < F1 * F2; i += 256) sW[i] = W2[i];
    if (threadIdx.x < F2) sb[threadIdx.x] = b2[threadIdx.x];
    __syncthreads();

    int tid = blockIdx.x * 64 + (threadIdx.x >> 2);
    int q   = threadIdx.x & 3;
    bool valid = tid < NN;
    int t = valid ? tid : NN - 1;

    const uint2* src = (const uint2*)g_hds;
    AGG_LOOP(src)

    float d = g_dinv[t];
    acc.x *= d; acc.y *= d; acc.z *= d; acc.w *= d;

    // assemble all 16 features into each lane via width-4 shuffles
    float gg[16];
#pragma unroll
    for (int s = 0; s < 4; ++s) {
        gg[s*4+0] = __shfl_sync(0xffffffffu, acc.x, s, 4);
        gg[s*4+1] = __shfl_sync(0xffffffffu, acc.y, s, 4);
        gg[s*4+2] = __shfl_sync(0xffffffffu, acc.z, s, 4);
        gg[s*4+3] = __shfl_sync(0xffffffffu, acc.w, s, 4);
    }

    // each lane computes 10 of the 40 outputs
    float o[10];
#pragma unroll
    for (int j = 0; j < 10; ++j) o[j] = sb[q * 10 + j];
#pragma unroll
    for (int k = 0; k < 16; ++k) {
        float gv = gg[k];
        const float* wr = sW + k * F2 + q * 10;
#pragma unroll
        for (int j = 0; j < 10; ++j) o[j] += gv * wr[j];
    }

    if (valid) {
        // q*10 floats = 40B offset, 8B-aligned -> 5 STG.64 instead of 10 STG.32
        float2* op = (float2*)(out + (size_t)t * F2 + q * 10);
#pragma unroll
        for (int j = 0; j < 5; ++j) op[j] = make_float2(o[j*2], o[j*2+1]);
    }
}

// ---------------------------------------------------------------------------
extern "C" void kernel_launch(void* const* d_in, const int* in_sizes, int n_in,
                              void* d_out, int out_size) {
    const float* x  = (const float*)d_in[0];
    const int*   ei = (const int*)  d_in[1];
    const float* W1 = (const float*)d_in[2];
    const float* b1 = (const float*)d_in[3];
    const float* W2 = (const float*)d_in[4];
    const float* b2 = (const float*)d_in[5];
    float* out = (float*)d_out;

    int E = in_sizes[1] / 2;                  // 3,200,000
    if (E > EEMAX) E = EEMAX;
    const int* row = ei;
    const int* col = ei + E;
    int E4 = E / 4;

    const int TB = 256;
    int nb_g  = (NN + 127) / 128;             // gemm1 blocks (128 nodes each)
    int nb_n  = (NN + TB - 1) / TB;
    int nb_e4 = (E4 + (E - E4 * 4) + TB - 1) / TB;
    int nb_a  = (NN + 63) / 64;               // agg blocks (4 thr/node)

    // one-time host-side resources (created on first call, reused by capture)
    static cudaStream_t sB = nullptr;
    static cudaEvent_t evStart = nullptr, evGemm = nullptr;
    static void* cntPtr = nullptr;
    if (!sB) {
        cudaStreamCreateWithFlags(&sB, cudaStreamNonBlocking);
        cudaEventCreateWithFlags(&evStart, cudaEventDisableTiming);
        cudaEventCreateWithFlags(&evGemm,  cudaEventDisableTiming);
        cudaGetSymbolAddress(&cntPtr, g_cnt);
    }

    cudaEventRecord(evStart, 0);              // fork point (t = 0)
    cudaStreamWaitEvent(sB, evStart, 0);

    // main stream: one-pass bucketed adjacency build
    cudaMemsetAsync(cntPtr, 0, NN * sizeof(int), 0);
    k_fill  <<<nb_e4, TB>>>(row, col, E4, E);

    // side stream: tensor-core gemm1, starts at t=0
    k_gemm1 <<<nb_g, TB, 0, sB>>>(x, W1);     // g_xw = x @ W1 (HMMA)
    cudaEventRecord(evGemm, sB);

    cudaStreamWaitEvent(0, evGemm, 0);        // join gemm1
    k_scale <<<nb_n, TB>>>();                 // dinv + fp16 scaled src
    k_agg1  <<<nb_a, TB>>>(b1);               // agg1 (dropout fused) = ncu slot 5
    k_agg2  <<<nb_a, TB>>>(W2, b2, out);      // out (GEMM fused)
}

// round 16
// speedup vs baseline: 1.1976x; 1.1841x over previous
#include <cuda_runtime.h>
#include <cuda_fp16.h>

#define NN    100000
#define EEMAX 3200000
#define F1    16
#define F2    40
#define DIN   512
#define CAP   128               // bucket capacity; deg ~ Poisson(32), P(>128) ~ 0

// Scratch (static device globals — no allocation allowed)
__device__ int    g_cnt [NN];          // edge in-degree (without self-loop)
__device__ int    g_adj [NN * CAP];    // bucketed adjacency: sources per target
__device__ float  g_dinv[NN];
__device__ float  g_xw  [NN * F1];     // x @ W1 (fp32, unscaled)
__device__ __half g_src [NN * F1];     // fp16: dinv * xw
__device__ __half g_hds [NN * F1];     // fp16: dinv * dropout(h + b1)

// ---------------------------------------------------------------------------
__global__ void k_nop() {}   // scheduling shims: delay fill's first block so
                             // gemm1 (side stream) grabs the SMs first.
                             // R13 vs R14/R15 A/B: removing these cost +22us.

// ---------------------------------------------------------------------------
// Single-pass adjacency build: count + bucket-append (no scan, no second pass)
__global__ void k_fill(const int* __restrict__ row, const int* __restrict__ col,
                       int E4, int E) {
    int i = blockIdx.x * blockDim.x + threadIdx.x;
    if (i < E4) {
        int4 r = ((const int4*)row)[i];
        int4 c = ((const int4*)col)[i];
        int p;
        p = atomicAdd(&g_cnt[c.x], 1); if (p < CAP) g_adj[c.x * CAP + p] = r.x;
        p = atomicAdd(&g_cnt[c.y], 1); if (p < CAP) g_adj[c.y * CAP + p] = r.y;
        p = atomicAdd(&g_cnt[c.z], 1); if (p < CAP) g_adj[c.z * CAP + p] = r.z;
        p = atomicAdd(&g_cnt[c.w], 1); if (p < CAP) g_adj[c.w * CAP + p] = r.w;
    } else {
        int e = E4 * 4 + (i - E4);               // tail (E%4 != 0 only)
        if (e < E) {
            int c = col[e], p = atomicAdd(&g_cnt[c], 1);
            if (p < CAP) g_adj[c * CAP + p] = row[e];
        }
    }
}

// ---------------------------------------------------------------------------
__device__ __forceinline__ unsigned cvt2(float lo, float hi) {
    __half2 h = __floats2half2_rn(lo, hi);
    return *(unsigned*)&h;
}

// gemm1 (TENSOR CORE, k-permuted float4 A-loads) — R13-validated config.
__global__ __launch_bounds__(256) void k_gemm1(const float* __restrict__ x,
                                               const float* __restrict__ W1) {
    __shared__ unsigned sB[32][2][2][32];        // [kstep][nhalf][breg][lane] 16KB

    int t = threadIdx.x;
    // pack B fragments with permuted k: slot (r,b) of lane l -> phys k = 4*(l&3)+2r+b
    for (int i = t; i < 32 * 2 * 2 * 32; i += 256) {
        int l = i & 31;
        int r = (i >> 5) & 1;
        int h = (i >> 6) & 1;
        int j = i >> 7;
        int kp = j * 16 + 4 * (l & 3) + 2 * r;   // physical k (permuted)
        int n  = h * 8 + (l >> 2);
        ((unsigned*)sB)[i] = cvt2(W1[kp * 16 + n], W1[(kp + 1) * 16 + n]);
    }
    __syncthreads();

    int w = t >> 5, l = t & 31;
    int v0 = blockIdx.x * 128 + w * 16;          // this warp's 16 nodes
    int gr = l >> 2;                             // fragment row group 0..7
    int ca = 4 * (l & 3);                        // A-load offset (physical k)
    int co = 2 * (l & 3);                        // output col pair base
    int v_lo = v0 + gr, v_hi = v0 + gr + 8;
    const float* plo = x + (size_t)min(v_lo, NN - 1) * DIN;
    const float* phi = x + (size_t)min(v_hi, NN - 1) * DIN;

    float d0 = 0.f, d1 = 0.f, d2 = 0.f, d3 = 0.f;   // n-half 0 accums
    float e0 = 0.f, e1 = 0.f, e2 = 0.f, e3 = 0.f;   // n-half 1 accums

#pragma unroll 4
    for (int j = 0; j < 32; ++j) {               // k-steps of 16
        int k0 = j * 16;
        float4 flo = *(const float4*)(plo + k0 + ca);
        float4 fhi = *(const float4*)(phi + k0 + ca);
        unsigned a0 = cvt2(flo.x, flo.y);
        unsigned a1 = cvt2(fhi.x, fhi.y);
        unsigned a2 = cvt2(flo.z, flo.w);
        unsigned a3 = cvt2(fhi.z, fhi.w);
        unsigned b00 = sB[j][0][0][l], b01 = sB[j][0][1][l];
        unsigned b10 = sB[j][1][0][l], b11 = sB[j][1][1][l];
        asm volatile(
            "mma.sync.aligned.m16n8k16.row.col.f32.f16.f16.f32 "
            "{%0,%1,%2,%3}, {%4,%5,%6,%7}, {%8,%9}, {%0,%1,%2,%3};"
            : "+f"(d0), "+f"(d1), "+f"(d2), "+f"(d3)
            : "r"(a0), "r"(a1), "r"(a2), "r"(a3), "r"(b00), "r"(b01));
        asm volatile(
            "mma.sync.aligned.m16n8k16.row.col.f32.f16.f16.f32 "
            "{%0,%1,%2,%3}, {%4,%5,%6,%7}, {%8,%9}, {%0,%1,%2,%3};"
            : "+f"(e0), "+f"(e1), "+f"(e2), "+f"(e3)
            : "r"(a0), "r"(a1), "r"(a2), "r"(a3), "r"(b10), "r"(b11));
    }

    if (v_lo < NN) {
        *(float2*)(g_xw + (size_t)v_lo * F1 + co)     = make_float2(d0, d1);
        *(float2*)(g_xw + (size_t)v_lo * F1 + 8 + co) = make_float2(e0, e1);
    }
    if (v_hi < NN) {
        *(float2*)(g_xw + (size_t)v_hi * F1 + co)     = make_float2(d2, d3);
        *(float2*)(g_xw + (size_t)v_hi * F1 + 8 + co) = make_float2(e2, e3);
    }
}

// scale: dinv = rsqrt(cnt+1); g_src = fp16(dinv * g_xw)   (one thread per node)
__global__ void k_scale() {
    int v = blockIdx.x * blockDim.x + threadIdx.x;
    if (v >= NN) return;
    float d = rsqrtf((float)(g_cnt[v] + 1));
    g_dinv[v] = d;
    const float4* xp = (const float4*)(g_xw + (size_t)v * F1);
    uint4 o[2];
    __half2* hp = (__half2*)o;
#pragma unroll
    for (int q = 0; q < 4; ++q) {
        float4 a = xp[q];
        hp[q * 2 + 0] = __floats2half2_rn(d * a.x, d * a.y);
        hp[q * 2 + 1] = __floats2half2_rn(d * a.z, d * a.w);
    }
    ((uint4*)g_src)[v * 2 + 0] = o[0];
    ((uint4*)g_src)[v * 2 + 1] = o[1];
}

// ---------------------------------------------------------------------------
// JAX threefry2x32 (partitionable): key=(0,42), ctr=(0, idx).
// bernoulli(0.5) keep  <=>  MSB(out0 ^ out1) == 0
__device__ __forceinline__ unsigned tf_keep_bits(unsigned idx) {
    const unsigned k0 = 0u, k1 = 42u, k2 = 0u ^ 42u ^ 0x1BD11BDAu;
    unsigned x0 = k0;
    unsigned x1 = idx + k1;
#define TFR(r) { x0 += x1; x1 = (x1 << (r)) | (x1 >> (32 - (r))); x1 ^= x0; }
    TFR(13) TFR(15) TFR(26) TFR(6)   x0 += k1; x1 += k2 + 1u;
    TFR(17) TFR(29) TFR(16) TFR(24)  x0 += k2; x1 += k0 + 2u;
    TFR(13) TFR(15) TFR(26) TFR(6)   x0 += k0; x1 += k1 + 3u;
    TFR(17) TFR(29) TFR(16) TFR(24)  x0 += k1; x1 += k2 + 4u;
    TFR(13) TFR(15) TFR(26) TFR(6)   x0 += k2; x1 += k0 + 5u;
#undef TFR
    return x0 ^ x1;
}

// ---------------------------------------------------------------------------
// fp16 gather: 4 threads/node, q in [0,4) owns 4 halves (8B). 8-deep unroll,
// adjacency read as int4 (R13-validated config).
__device__ __forceinline__ void h4acc(uint2 u, float4& acc) {
    float2 f0 = __half22float2(*(__half2*)&u.x);
    float2 f1 = __half22float2(*(__half2*)&u.y);
    acc.x += f0.x; acc.y += f0.y; acc.z += f1.x; acc.w += f1.y;
}

#define AGG_LOOP(SRCP)                                                         \
    float4 acc = make_float4(0.f, 0.f, 0.f, 0.f);                              \
    { uint2 us = SRCP[t * 4 + q]; h4acc(us, acc); }   /* self-loop */          \
    {                                                                          \
        int cnt = g_cnt[t]; if (cnt > CAP) cnt = CAP;                          \
        const int* ap = g_adj + t * CAP;                                       \
        int pos = 0;                                                           \
        for (; pos + 8 <= cnt; pos += 8) {                                     \
            int4 a0 = ((const int4*)(ap + pos))[0];                            \
            int4 a1 = ((const int4*)(ap + pos))[1];                            \
            uint2 u0 = SRCP[a0.x*4+q], u1 = SRCP[a0.y*4+q];                    \
            uint2 u2 = SRCP[a0.z*4+q], u3 = SRCP[a0.w*4+q];                    \
            uint2 u4 = SRCP[a1.x*4+q], u5 = SRCP[a1.y*4+q];                    \
            uint2 u6 = SRCP[a1.z*4+q], u7 = SRCP[a1.w*4+q];                    \
            h4acc(u0, acc); h4acc(u1, acc); h4acc(u2, acc); h4acc(u3, acc);    \
            h4acc(u4, acc); h4acc(u5, acc); h4acc(u6, acc); h4acc(u7, acc);    \
        }                                                                      \
        for (; pos < cnt; ++pos) { uint2 u = SRCP[ap[pos]*4+q]; h4acc(u, acc);}\
    }

// Layer-1 aggregation (4 threads per node) + dropout fused; fp16 out.
__global__ __launch_bounds__(256) void k_agg1(const float* __restrict__ b1) {
    int t = blockIdx.x * 64 + (threadIdx.x >> 2);
    int q = threadIdx.x & 3;
    if (t >= NN) return;

    const uint2* src = (const uint2*)g_src;
    AGG_LOOP(src)

    float d = g_dinv[t];
    float4 bb = ((const float4*)b1)[q];
    unsigned idx = (unsigned)(t * 16 + q * 4);
    float h0 = d * acc.x + bb.x, h1 = d * acc.y + bb.y;
    float h2 = d * acc.z + bb.z, h3 = d * acc.w + bb.w;
    float o0 = (tf_keep_bits(idx + 0) & 0x80000000u) ? 0.0f : 2.0f * d * h0;
    float o1 = (tf_keep_bits(idx + 1) & 0x80000000u) ? 0.0f : 2.0f * d * h1;
    float o2 = (tf_keep_bits(idx + 2) & 0x80000000u) ? 0.0f : 2.0f * d * h2;
    float o3 = (tf_keep_bits(idx + 3) & 0x80000000u) ? 0.0f : 2.0f * d * h3;
    uint2 o;
    ((__half2*)&o.x)[0] = __floats2half2_rn(o0, o1);
    ((__half2*)&o.y)[0] = __floats2half2_rn(o2, o3);
    ((uint2*)g_hds)[t * 4 + q] = o;
}

// Layer-2 aggregation + fused (16x40 GEMM + b2); fp32 out written directly.
__global__ __launch_bounds__(256) void k_agg2(const float* __restrict__ W2,
                                              const float* __restrict__ b2,
                                              float* __restrict__ out) {
    __shared__ float sW[F1 * F2];
    __shared__ float sb[F2];
    for (int i = threadIdx.x; i < F1 * F2; i += 256) sW[i] = W2[i];
    if (threadIdx.x < F2) sb[threadIdx.x] = b2[threadIdx.x];
    __syncthreads();

    int tid = blockIdx.x * 64 + (threadIdx.x >> 2);
    int q   = threadIdx.x & 3;
    bool valid = tid < NN;
    int t = valid ? tid : NN - 1;

    const uint2* src = (const uint2*)g_hds;
    AGG_LOOP(src)

    float d = g_dinv[t];
    acc.x *= d; acc.y *= d; acc.z *= d; acc.w *= d;

    // assemble all 16 features into each lane via width-4 shuffles
    float gg[16];
#pragma unroll
    for (int s = 0; s < 4; ++s) {
        gg[s*4+0] = __shfl_sync(0xffffffffu, acc.x, s, 4);
        gg[s*4+1] = __shfl_sync(0xffffffffu, acc.y, s, 4);
        gg[s*4+2] = __shfl_sync(0xffffffffu, acc.z, s, 4);
        gg[s*4+3] = __shfl_sync(0xffffffffu, acc.w, s, 4);
    }

    // each lane computes 10 of the 40 outputs
    float o[10];
#pragma unroll
    for (int j = 0; j < 10; ++j) o[j] = sb[q * 10 + j];
#pragma unroll
    for (int k = 0; k < 16; ++k) {
        float gv = gg[k];
        const float* wr = sW + k * F2 + q * 10;
#pragma unroll
        for (int j = 0; j < 10; ++j) o[j] += gv * wr[j];
    }

    if (valid) {
        // q*10 floats = 40B offset, 8B-aligned -> 5 STG.64 instead of 10 STG.32
        float2* op = (float2*)(out + (size_t)t * F2 + q * 10);
#pragma unroll
        for (int j = 0; j < 5; ++j) op[j] = make_float2(o[j*2], o[j*2+1]);
    }
}

// ---------------------------------------------------------------------------
extern "C" void kernel_launch(void* const* d_in, const int* in_sizes, int n_in,
                              void* d_out, int out_size) {
    const float* x  = (const float*)d_in[0];
    const int*   ei = (const int*)  d_in[1];
    const float* W1 = (const float*)d_in[2];
    const float* b1 = (const float*)d_in[3];
    const float* W2 = (const float*)d_in[4];
    const float* b2 = (const float*)d_in[5];
    float* out = (float*)d_out;

    int E = in_sizes[1] / 2;                  // 3,200,000
    if (E > EEMAX) E = EEMAX;
    const int* row = ei;
    const int* col = ei + E;
    int E4 = E / 4;

    const int TB = 256;
    int nb_g  = (NN + 127) / 128;             // gemm1 blocks (128 nodes each)
    int nb_n  = (NN + TB - 1) / TB;
    int nb_e4 = (E4 + (E - E4 * 4) + TB - 1) / TB;
    int nb_a  = (NN + 63) / 64;               // agg blocks (4 thr/node)

    // one-time host-side resources (created on first call, reused by capture)
    static cudaStream_t sB = nullptr;
    static cudaEvent_t evStart = nullptr, evGemm = nullptr;
    static void* cntPtr = nullptr;
    if (!sB) {
        int loPrio, hiPrio;
        cudaDeviceGetStreamPriorityRange(&loPrio, &hiPrio);
        cudaStreamCreateWithPriority(&sB, cudaStreamNonBlocking, hiPrio);
        cudaEventCreateWithFlags(&evStart, cudaEventDisableTiming);
        cudaEventCreateWithFlags(&evGemm,  cudaEventDisableTiming);
        cudaGetSymbolAddress(&cntPtr, g_cnt);
    }

    cudaEventRecord(evStart, 0);              // fork point (t = 0)
    cudaStreamWaitEvent(sB, evStart, 0);

    // scheduling shims (R13-validated): delay fill so gemm1 starts first
    k_nop <<<1, 32>>>();
    k_nop <<<1, 32>>>();

    // main stream: one-pass bucketed adjacency build
    cudaMemsetAsync(cntPtr, 0, NN * sizeof(int), 0);
    k_fill  <<<nb_e4, TB>>>(row, col, E4, E);

    // side stream (high priority): tensor-core gemm1
    k_gemm1 <<<nb_g, TB, 0, sB>>>(x, W1);     // g_xw = x @ W1 (HMMA)
    cudaEventRecord(evGemm, sB);

    cudaStreamWaitEvent(0, evGemm, 0);        // join gemm1
    k_scale <<<nb_n, TB>>>();                 // dinv + fp16 scaled src
    k_agg1  <<<nb_a, TB>>>(b1);               // agg1 (dropout fused)
    k_agg2  <<<nb_a, TB>>>(W2, b2, out);      // out (GEMM fused)
}